// round 6
// baseline (speedup 1.0000x reference)
#include <cuda_runtime.h>

#define NN 384
#define DD 128
#define MARGIN_F 0.2f
#define APB 3
#define NBLK (NN / APB)     // 128 triplet blocks
#define TS 32               // gemm tile size
#define SPAD 33             // padded smem row stride (floats)
#define MAXPOS 64

// Scratch (no allocations allowed)
__device__ float g_dot[NN * NN];   // feat @ feat^T
__device__ float g_r[NN];          // diagonal (squared norms)
__device__ float g_total;
__device__ float g_count;
__device__ unsigned int g_ctr;

// ---- GEMM: G = feat @ feat^T, 32x32 tiles, 2x2 micro-tiles ----
__global__ void __launch_bounds__(256) gemm_k(const float* __restrict__ feat) {
    __shared__ float As[TS][SPAD];
    __shared__ float Bs[TS][SPAD];

    const int t  = threadIdx.x;
    const int tx = t & 15;          // j micro index
    const int ty = t >> 4;          // i micro index
    const int i0 = blockIdx.y * TS;
    const int j0 = blockIdx.x * TS;

    const int lr = t >> 3;          // staging row 0..31
    const int lk = (t & 7) * 4;     // staging k base (float4)

    float c00 = 0.f, c01 = 0.f, c10 = 0.f, c11 = 0.f;

#pragma unroll
    for (int kc = 0; kc < DD; kc += TS) {
        const float4 av = *reinterpret_cast<const float4*>(feat + (i0 + lr) * DD + kc + lk);
        const float4 bv = *reinterpret_cast<const float4*>(feat + (j0 + lr) * DD + kc + lk);
        As[lr][lk + 0] = av.x; As[lr][lk + 1] = av.y;
        As[lr][lk + 2] = av.z; As[lr][lk + 3] = av.w;
        Bs[lr][lk + 0] = bv.x; Bs[lr][lk + 1] = bv.y;
        Bs[lr][lk + 2] = bv.z; Bs[lr][lk + 3] = bv.w;
        __syncthreads();

#pragma unroll
        for (int k = 0; k < TS; k++) {
            const float a0 = As[2 * ty][k];
            const float a1 = As[2 * ty + 1][k];
            const float b0 = Bs[2 * tx][k];
            const float b1 = Bs[2 * tx + 1][k];
            c00 += a0 * b0; c01 += a0 * b1;
            c10 += a1 * b0; c11 += a1 * b1;
        }
        __syncthreads();
    }

    const int gi = i0 + 2 * ty;
    const int gj = j0 + 2 * tx;
    *reinterpret_cast<float2*>(&g_dot[gi * NN + gj])       = make_float2(c00, c01);
    *reinterpret_cast<float2*>(&g_dot[(gi + 1) * NN + gj]) = make_float2(c10, c11);
    if (blockIdx.x == blockIdx.y && tx == ty) {
        g_r[gi]     = c00;   // dot(i,i)
        g_r[gi + 1] = c11;
    }
}

// ---- triplet kernel: 3 anchors per block, 384 threads (one per column) ----
__global__ void __launch_bounds__(NN) trip_k(const int* __restrict__ y,
                                             float* __restrict__ out) {
    const int t  = threadIdx.x;
    const int ab = blockIdx.x * APB;
    const int w = t >> 5, lane = t & 31;
    const unsigned FULL = 0xFFFFFFFFu;

    __shared__ int   ys[NN];
    __shared__ float ras[APB];
    __shared__ float pos_d[APB][MAXPOS];
    __shared__ int   wc[APB][12];
    __shared__ int   wbase[APB][12];
    __shared__ int   np_s[APB];
    __shared__ float red_f[12];

    ys[t] = y[t];
    if (t < APB) ras[t] = g_r[ab + t];
    const float rj = g_r[t];
    __syncthreads();

    // d2 rows in registers
    float d2r[APB];
#pragma unroll
    for (int m = 0; m < APB; m++) {
        const float dot = g_dot[(ab + m) * NN + t];
        d2r[m] = fmaxf(ras[m] + rj - 2.0f * dot, 0.0f);
    }

    // ballot compaction of positives
    bool isp[APB];
    unsigned pm[APB];
#pragma unroll
    for (int m = 0; m < APB; m++) {
        isp[m] = (ys[t] == ys[ab + m]) && (t != ab + m);
        pm[m] = __ballot_sync(FULL, isp[m]);
        if (lane == 0) wc[m][w] = __popc(pm[m]);
    }
    __syncthreads();
    if (t < APB) {
        int s = 0;
#pragma unroll
        for (int ww = 0; ww < 12; ww++) { wbase[t][ww] = s; s += wc[t][ww]; }
        np_s[t] = s;
    }
    __syncthreads();
#pragma unroll
    for (int m = 0; m < APB; m++) {
        if (isp[m]) {
            const int idx = wbase[m][w] + __popc(pm[m] & ((1u << lane) - 1u));
            pos_d[m][idx] = d2r[m] + MARGIN_F;
        }
    }
    __syncthreads();

    // phase B: for each anchor, thread t is a candidate negative
    float acc = 0.0f;
#pragma unroll
    for (int m = 0; m < APB; m++) {
        const int npm = np_s[m];
        if (ys[t] != ys[ab + m]) {
            const float dn = d2r[m];
            for (int i = 0; i < npm; i++) {
                const float v = pos_d[m][i] - dn;
                acc += (v > 0.0f) ? v : 0.0f;
            }
        }
    }

    // block reduction + global accumulate + last-block finalize
#pragma unroll
    for (int off = 16; off > 0; off >>= 1)
        acc += __shfl_down_sync(FULL, acc, off);
    if (lane == 0) red_f[w] = acc;
    __syncthreads();
    if (w == 0) {
        float af = (lane < 12) ? red_f[lane] : 0.0f;
#pragma unroll
        for (int off = 8; off > 0; off >>= 1)
            af += __shfl_down_sync(FULL, af, off);
        if (lane == 0) {
            const int cnt = np_s[0] * (NN - 1 - np_s[0])
                          + np_s[1] * (NN - 1 - np_s[1])
                          + np_s[2] * (NN - 1 - np_s[2]);
            atomicAdd(&g_total, af);
            atomicAdd(&g_count, (float)cnt);
            __threadfence();
            const unsigned done = atomicAdd(&g_ctr, 1u);
            if (done == NBLK - 1) {
                const float tot = atomicAdd(&g_total, 0.0f);
                const float cn  = atomicAdd(&g_count, 0.0f);
                out[0] = tot / cn;
                g_total = 0.0f;
                g_count = 0.0f;
                g_ctr   = 0u;
            }
        }
    }
}

extern "C" void kernel_launch(void* const* d_in, const int* in_sizes, int n_in,
                              void* d_out, int out_size) {
    const float* feat = (const float*)d_in[0];
    // d_in[1] = logits (unused by the loss)
    const int*   yv   = (const int*)d_in[2];
    float* out = (float*)d_out;

    gemm_k<<<dim3(NN / TS, NN / TS), 256>>>(feat);
    trip_k<<<NBLK, NN>>>(yv, out);
}